// round 11
// baseline (speedup 1.0000x reference)
#include <cuda_runtime.h>
#include <cstdint>

// g_tree: heap-indexed subtree sums, levels 0..20 (indices [1, 2^21)).
//   build_lower stores levels 12..20; build_top (1 block) stores levels 0..11.
// g_rec: 4-level descent records. For node i at levels {0,4,8,12,16},
//   g_rec[4i..4i+3] packs {t[2i]; t[4i],t[4i+2]; t[8i+evens]; t[16i+evens]}
//   (15 floats + pad = 64B) so one 64B load decides 4 levels.
// Levels 21..24 + the priority come from a 64B burst of the 16 leaves under
// the level-20 node. All sums use the identical left+right pairing as the
// reference's reshape(-1,2).sum(axis=1) => bitwise-exact descent.
#define BOUND (1 << 24)
__device__ float  g_tree[1 << 21];   // 8 MB
__device__ float4 g_rec[1 << 19];    // 8 MB (entries 4*i for i < 2^17)

// ---------------------------------------------------------------------------
// Build: each block reduces 4096 contiguous leaves; stores levels 20..12.
// Clean version: no fences/atomics, tiny smem (those cost ~6 us in R7/R9).
// ---------------------------------------------------------------------------
__global__ __launch_bounds__(256) void build_lower(const float* __restrict__ leaf) {
    const int b = blockIdx.x;           // 4096 blocks
    const int t = threadIdx.x;
    const int lane = t & 31;
    const int w = t >> 5;               // 8 warps
    __shared__ float s17[32];

    const float4* __restrict__ in = reinterpret_cast<const float4*>(leaf) + (size_t)b * 1024;

    float* g20 = g_tree + (1u << 20) + (size_t)b * 256;
    float* g19 = g_tree + (1u << 19) + (size_t)b * 128;
    float* g18 = g_tree + (1u << 18) + (size_t)b * 64;
    float* g17 = g_tree + (1u << 17) + (size_t)b * 32;

#pragma unroll
    for (int r = 0; r < 4; ++r) {
        const int q = r * 256 + t;                    // level-22 node id in block
        float4 a = in[q];                             // coalesced LDG.128
        float v = (a.x + a.y) + (a.z + a.w);          // level-22 value (exact pairing)
        float u;
        u = __shfl_down_sync(0xffffffffu, v, 1);  v += u;   // level 21 (not stored)
        u = __shfl_down_sync(0xffffffffu, v, 2);  v += u;   // level 20
        if (!(lane & 3))  g20[r * 64 + w * 8 + (lane >> 2)] = v;
        u = __shfl_down_sync(0xffffffffu, v, 4);  v += u;   // level 19
        if (!(lane & 7))  g19[r * 32 + w * 4 + (lane >> 3)] = v;
        u = __shfl_down_sync(0xffffffffu, v, 8);  v += u;   // level 18
        if (!(lane & 15)) g18[r * 16 + w * 2 + (lane >> 4)] = v;
        u = __shfl_down_sync(0xffffffffu, v, 16); v += u;   // level 17
        if (lane == 0) { g17[r * 8 + w] = v; s17[r * 8 + w] = v; }
    }
    __syncthreads();

    if (w == 0) {
        float v = s17[lane];
        float u;
        float* g16 = g_tree + (1u << 16) + (size_t)b * 16;
        float* g15 = g_tree + (1u << 15) + (size_t)b * 8;
        float* g14 = g_tree + (1u << 14) + (size_t)b * 4;
        float* g13 = g_tree + (1u << 13) + (size_t)b * 2;
        float* g12 = g_tree + (1u << 12) + (size_t)b;
        u = __shfl_down_sync(0xffffffffu, v, 1);  v += u;
        if (!(lane & 1))  g16[lane >> 1] = v;
        u = __shfl_down_sync(0xffffffffu, v, 2);  v += u;
        if (!(lane & 3))  g15[lane >> 2] = v;
        u = __shfl_down_sync(0xffffffffu, v, 4);  v += u;
        if (!(lane & 7))  g14[lane >> 3] = v;
        u = __shfl_down_sync(0xffffffffu, v, 8);  v += u;
        if (!(lane & 15)) g13[lane >> 4] = v;
        u = __shfl_down_sync(0xffffffffu, v, 16); v += u;
        if (lane == 0)    g12[0] = v;
    }
}

// ---------------------------------------------------------------------------
// build_top: 1 block, 1024 threads. Reads level 12 (heap [4096, 8192)),
// reduces in smem, stores levels 11..0 into g_tree[0..4096) (slot 0 = pad).
// ---------------------------------------------------------------------------
__global__ __launch_bounds__(1024) void build_top() {
    __shared__ float s[8192];
    const int t = threadIdx.x;
    float4* s4p = reinterpret_cast<float4*>(s);
    const float4* g4 = reinterpret_cast<const float4*>(g_tree);
    for (int i = t; i < 1024; i += 1024) s4p[1024 + i] = g4[1024 + i];
    if (t == 0) s[0] = 0.0f;
    __syncthreads();
#pragma unroll
    for (int n = 2048; n >= 1; n >>= 1) {
        for (int i = t; i < n; i += 1024)
            s[n + i] = s[2 * (n + i)] + s[2 * (n + i) + 1];
        __syncthreads();
    }
    float4* g4w = reinterpret_cast<float4*>(g_tree);
    for (int i = t; i < 1024; i += 1024) g4w[i] = s4p[i];
}

// ---------------------------------------------------------------------------
// build_rec: one thread per record node i (levels 0,4,8,12,16 => 69905
// entries). Reads the 15 needed sums with vector loads (coalesced in i),
// writes the 64B record. Requires full g_tree (levels 1..20).
// ---------------------------------------------------------------------------
__global__ __launch_bounds__(256) void build_rec() {
    const int tid = blockIdx.x * 256 + threadIdx.x;
    int i;
    if      (tid < 65536)  i = 65536 + tid;            // level 16
    else if (tid < 69632)  i = 4096 + (tid - 65536);   // level 12
    else if (tid < 69888)  i = 256  + (tid - 69632);   // level 8
    else if (tid < 69904)  i = 16   + (tid - 69888);   // level 4
    else if (tid == 69904) i = 1;                      // level 0
    else return;

    const float  a  = g_tree[2 * (size_t)i];
    const float4 B  = *reinterpret_cast<const float4*>(&g_tree[4  * (size_t)i]);
    const float4 C0 = *reinterpret_cast<const float4*>(&g_tree[8  * (size_t)i]);
    const float4 C1 = *reinterpret_cast<const float4*>(&g_tree[8  * (size_t)i + 4]);
    const float4 D0 = *reinterpret_cast<const float4*>(&g_tree[16 * (size_t)i]);
    const float4 D1 = *reinterpret_cast<const float4*>(&g_tree[16 * (size_t)i + 4]);
    const float4 D2 = *reinterpret_cast<const float4*>(&g_tree[16 * (size_t)i + 8]);
    const float4 D3 = *reinterpret_cast<const float4*>(&g_tree[16 * (size_t)i + 12]);

    float4* r = &g_rec[4 * (size_t)i];
    r[0] = make_float4(a,    B.x,  B.z,  C0.x);   // a, b0, b2, c0
    r[1] = make_float4(C0.z, C1.x, C1.z, D0.x);   // c2, c4, c6, d0
    r[2] = make_float4(D0.z, D1.x, D1.z, D2.x);   // d2, d4, d6, d8
    r[3] = make_float4(D2.z, D3.x, D3.z, 0.0f);   // d10, d12, d14, pad
}

// ---------------------------------------------------------------------------
// Descend: pure-global (no smem, no barriers), 512 blocks x 128 threads.
// 5 dependent 64B record loads resolve levels 1..20 (4 levels each), then a
// 64B burst of the 16 leaves under the level-20 node resolves levels 21..24
// and the priority. 6 dependent memory rounds total (was 10 in R7).
// ---------------------------------------------------------------------------
__global__ __launch_bounds__(128) void descend(const float* __restrict__ leaf,
                                               const float* __restrict__ frac,
                                               float* __restrict__ out,
                                               int batch) {
    const int q = blockIdx.x * 128 + threadIdx.x;
    if (q >= batch) return;

    float v = frac[q] * __ldg(&g_tree[1]);
    int idx = 1;

#pragma unroll
    for (int r5 = 0; r5 < 5; ++r5) {
        const float4* rp = g_rec + 4 * (size_t)idx;
        float4 r0 = __ldg(rp);
        float4 r1 = __ldg(rp + 1);
        float4 r2 = __ldg(rp + 2);
        float4 r3 = __ldg(rp + 3);

        bool x1 = (r0.x < v);                 v = x1 ? (v - r0.x) : v;   // level +1
        float lb = x1 ? r0.z : r0.y;
        bool x2 = (lb < v);                   v = x2 ? (v - lb) : v;     // level +2
        float lc = x1 ? (x2 ? r1.z : r1.y) : (x2 ? r1.x : r0.w);
        bool x3 = (lc < v);                   v = x3 ? (v - lc) : v;     // level +3
        float e0 = x3 ? r2.x : r1.w;          // (x1,x2)=(0,0): d0/d2
        float e1 = x3 ? r2.z : r2.y;          // (0,1): d4/d6
        float e2 = x3 ? r3.x : r2.w;          // (1,0): d8/d10
        float e3 = x3 ? r3.z : r3.y;          // (1,1): d12/d14
        float ld = x1 ? (x2 ? e3 : e2) : (x2 ? e1 : e0);
        bool x4 = (ld < v);                   v = x4 ? (v - ld) : v;     // level +4

        idx = 16 * idx + 8 * (int)x1 + 4 * (int)x2 + 2 * (int)x3 + (int)x4;
    }

    // idx at level 20. Burst the 16 leaves under it (64B aligned, 1 line).
    const int base = (idx << 4) - BOUND;
    const float4* lp = reinterpret_cast<const float4*>(leaf + base);
    float4 A = __ldg(lp);
    float4 B = __ldg(lp + 1);
    float4 C = __ldg(lp + 2);
    float4 D = __ldg(lp + 3);

    float s8_0 = A.x + A.y, s8_2 = B.x + B.y;
    float s8_4 = C.x + C.y, s8_6 = D.x + D.y;
    float s4_0 = s8_0 + (A.z + A.w), s4_1 = s8_2 + (B.z + B.w);
    float s4_2 = s8_4 + (C.z + C.w);
    float s2_0 = s4_0 + s4_1;

    bool r1 = (s2_0 < v); v = r1 ? (v - s2_0) : v;          // level 21
    float l22 = r1 ? s4_2 : s4_0;
    bool r2 = (l22 < v);  v = r2 ? (v - l22) : v;           // level 22
    float l23 = r1 ? (r2 ? s8_6 : s8_4) : (r2 ? s8_2 : s8_0);
    bool r3 = (l23 < v);  v = r3 ? (v - l23) : v;           // level 23
    float4 P = r1 ? C : A;
    float4 Q = r1 ? D : B;
    float4 R = r2 ? Q : P;
    float e0 = r3 ? R.z : R.x;
    float e1 = r3 ? R.w : R.y;
    bool r4 = (e0 < v);                                     // level 24
    float prio = r4 ? e1 : e0;

    const int leafIdx = base + 8 * (int)r1 + 4 * (int)r2 + 2 * (int)r3 + (int)r4;
    out[q] = (float)leafIdx;      // exact in f32 (< 2^24)
    out[batch + q] = prio;
}

extern "C" void kernel_launch(void* const* d_in, const int* in_sizes, int n_in,
                              void* d_out, int out_size) {
    const float* leaf = (const float*)d_in[0];
    const float* frac = (const float*)d_in[1];
    float* out = (float*)d_out;
    const int batch = in_sizes[1];

    build_lower<<<BOUND / 4096, 256>>>(leaf);
    build_top<<<1, 1024>>>();
    build_rec<<<(69905 + 255) / 256, 256>>>();
    descend<<<(batch + 127) / 128, 128>>>(leaf, frac, out, batch);
}